// round 14
// baseline (speedup 1.0000x reference)
#include <cuda_runtime.h>
#include <cuda_fp16.h>
#include <cstdint>

__device__ __half g_X[25165824];    // [m=(n,l,c)][v] fp16
__device__ __half g_A[3145728];     // A [v][w] fp16
__device__ __half g_At[3145728];    // A^T [w][v] fp16
__device__ __half g_AsqT[3145728];  // (A^2)^T [w][v] fp16
__device__ __half g_P[176160768];   // planes [cc][n][l][w] fp16
__device__ __half g_O[50331648];    // [m=(n,l,w)][o] fp16
__device__ __half g_W2[14336];      // [o][k] fp16

__device__ __forceinline__ void cp16(void* s, const void* g){
  unsigned sa = (unsigned)__cvta_generic_to_shared(s);
  asm volatile("cp.async.cg.shared.global [%0], [%1], 16;\n" :: "r"(sa), "l"(g));
}
__device__ __forceinline__ void cpcommit(){ asm volatile("cp.async.commit_group;\n"); }
__device__ __forceinline__ void ldsm4(unsigned* r, unsigned a){
  asm volatile("ldmatrix.sync.aligned.m8n8.x4.shared.b16 {%0,%1,%2,%3}, [%4];"
    : "=r"(r[0]), "=r"(r[1]), "=r"(r[2]), "=r"(r[3]) : "r"(a));
}
__device__ __forceinline__ void ldsm4t(unsigned* r, unsigned a){
  asm volatile("ldmatrix.sync.aligned.m8n8.x4.trans.shared.b16 {%0,%1,%2,%3}, [%4];"
    : "=r"(r[0]), "=r"(r[1]), "=r"(r[2]), "=r"(r[3]) : "r"(a));
}
__device__ __forceinline__ void mma16(float* d, const unsigned* a, const unsigned* b){
  asm volatile("mma.sync.aligned.m16n8k16.row.col.f32.f16.f16.f32 "
    "{%0,%1,%2,%3},{%4,%5,%6,%7},{%8,%9},{%0,%1,%2,%3};\n"
    : "+f"(d[0]), "+f"(d[1]), "+f"(d[2]), "+f"(d[3])
    : "r"(a[0]), "r"(a[1]), "r"(a[2]), "r"(a[3]), "r"(b[0]), "r"(b[1]));
}

__global__ void pack_a_k(const float* __restrict__ a0, const float* __restrict__ a1,
                         const float* __restrict__ a2){
  __shared__ float tsm[32][33];
  int z = blockIdx.z;
  const float* A = (z == 0) ? a0 : ((z == 1) ? a1 : a2);
  size_t zo = (size_t)z << 20;
  int v0 = blockIdx.y * 32, w0 = blockIdx.x * 32;
  int cl = threadIdx.x & 31, rg = threadIdx.x >> 5;
  #pragma unroll
  for (int i = 0; i < 4; i++){
    int row = rg + i * 8;
    float val = A[(size_t)(v0 + row) * 1024 + w0 + cl];
    g_A[zo + (size_t)(v0 + row) * 1024 + w0 + cl] = __float2half_rn(val);
    tsm[row][cl] = val;
  }
  __syncthreads();
  #pragma unroll
  for (int i = 0; i < 4; i++){
    int wr = rg + i * 8;
    g_At[zo + (size_t)(w0 + wr) * 1024 + v0 + cl] = __float2half_rn(tsm[cl][wr]);
  }
}
__global__ void pack_w_k(const float* __restrict__ W){
  int i = blockIdx.x * 256 + threadIdx.x;
  if (i < 14336) g_W2[i] = __float2half_rn(W[i]);   // W is [o][k] row-major already
}
__global__ void pack_x_k(const float* __restrict__ x){
  __shared__ float sm[6656];
  int nc = blockIdx.x >> 1, h = blockIdx.x & 1, t = threadIdx.x;
  int n = nc >> 5, c = nc & 31;
  const float* src = x + (size_t)nc * 12288 + h * 6144;
  for (int i = t; i < 6144; i += 256) sm[(i / 12) * 13 + (i % 12)] = src[i];
  __syncthreads();
  for (int l = 0; l < 12; l++){
    __half* d1 = g_X + ((size_t)((n * 12 + l) * 32 + c)) * 1024 + h * 512;
    __half* d2 = g_P + ((size_t)((c * 64 + n) * 12 + l)) * 1024 + h * 512;
    for (int v = t; v < 512; v += 256){
      __half r = __float2half_rn(sm[v * 13 + l]);
      d1[v] = r; d2[v] = r;
    }
  }
}

// fp16 GEMM: CTA 128x128, 4 warps of 64x64, KTILE=64, 3-stage ring, 2 CTAs/SM.
// stage halfs: A[128][72]=9216, B[128][72]=9216 -> 18432 halfs = 36864 B. x3 = 110592
#define GSMEM 110592
__global__ __launch_bounds__(128, 2) void gemm_k(int mode){
  extern __shared__ __half smh[];
  const int t = threadIdx.x, lane = t & 31, wid = t >> 5;
  const int bx = blockIdx.x, by = blockIdx.y, bz = blockIdx.z;
  const __half *Ap, *Bp; int kb = 0, w0 = 0;
  if (mode == 0){
    size_t zo = (size_t)bz << 20;
    Ap = g_At + zo + (size_t)by * 131072;
    Bp = g_A  + zo + (size_t)bx * 131072;
  } else {
    Ap = g_X + (size_t)by * 131072;
    kb = bx >> 3; w0 = (bx & 7) * 128;
    Bp = ((kb & 1) ? g_AsqT : g_At) + ((size_t)(kb >> 1) << 20) + (size_t)w0 * 1024;
  }
  float acc[4][8][4];
  #pragma unroll
  for (int i = 0; i < 4; i++)
    #pragma unroll
    for (int j = 0; j < 8; j++)
      #pragma unroll
      for (int q = 0; q < 4; q++) acc[i][j][q] = 0.f;

  auto load_stage = [&](int kt, int s){
    __half* As = smh + s * 18432;
    __half* Bs = As + 9216;
    const __half* Ag = Ap + kt * 64;
    #pragma unroll
    for (int i = 0; i < 8; i++){
      int idx = t + i * 128, r = idx >> 3, q = idx & 7;
      cp16(As + r * 72 + q * 8, Ag + (size_t)r * 1024 + q * 8);
    }
    const __half* Bg = Bp + kt * 64;
    #pragma unroll
    for (int i = 0; i < 8; i++){
      int idx = t + i * 128, r = idx >> 3, q = idx & 7;
      cp16(Bs + r * 72 + q * 8, Bg + (size_t)r * 1024 + q * 8);
    }
  };
  load_stage(0, 0); cpcommit();
  load_stage(1, 1); cpcommit();

  const int wm = wid >> 1, wn = wid & 1;
  const unsigned sbase = (unsigned)__cvta_generic_to_shared(smh);
  const int tile = lane >> 3, rowin = lane & 7;
  const unsigned aoff = (wm * 64 + rowin + (tile & 1) * 8) * 144 + (tile >> 1) * 16;
  const unsigned boff = 18432 + (wn * 64 + (tile >> 1) * 8 + rowin) * 144 + (tile & 1) * 16;

  int sidx = 0; // stage of current kt
  for (int kt = 0; kt < 16; kt++){
    asm volatile("cp.async.wait_group 1;\n");
    __syncthreads();
    if (kt + 2 < 16){
      int s2 = sidx + 2; if (s2 >= 3) s2 -= 3;
      load_stage(kt + 2, s2);
    }
    cpcommit();
    unsigned sst = sbase + sidx * 36864;
    #pragma unroll
    for (int ksp = 0; ksp < 2; ksp++){
      unsigned af[2][4][4], bf[2][8][2];
      #pragma unroll
      for (int k2 = 0; k2 < 2; k2++){
        int ks = ksp * 2 + k2;
        #pragma unroll
        for (int mf = 0; mf < 4; mf++)
          ldsm4(af[k2][mf], sst + aoff + mf * 2304 + ks * 32);
        #pragma unroll
        for (int j = 0; j < 4; j++){
          unsigned r4[4];
          ldsm4(r4, sst + boff + j * 2304 + ks * 32);
          bf[k2][2*j][0] = r4[0]; bf[k2][2*j][1] = r4[1];
          bf[k2][2*j+1][0] = r4[2]; bf[k2][2*j+1][1] = r4[3];
        }
      }
      #pragma unroll
      for (int k2 = 0; k2 < 2; k2++)
        #pragma unroll
        for (int mf = 0; mf < 4; mf++)
          #pragma unroll
          for (int nf = 0; nf < 8; nf++) mma16(acc[mf][nf], af[k2][mf], bf[k2][nf]);
    }
    if (++sidx == 3) sidx = 0;
  }
  asm volatile("cp.async.wait_group 0;\n");
  __syncthreads();

  if (mode == 0){
    #pragma unroll
    for (int mf = 0; mf < 4; mf++){
      int r = by * 128 + wm * 64 + mf * 16 + (lane >> 2);
      #pragma unroll
      for (int nf = 0; nf < 8; nf++){
        int cc = bx * 128 + wn * 64 + nf * 8 + (lane & 3) * 2;
        __half2 lo = __floats2half2_rn(acc[mf][nf][0], acc[mf][nf][1]);
        __half2 hi = __floats2half2_rn(acc[mf][nf][2], acc[mf][nf][3]);
        *(__half2*)(g_AsqT + ((size_t)bz << 20) + (size_t)r * 1024 + cc)       = lo;
        *(__half2*)(g_AsqT + ((size_t)bz << 20) + (size_t)(r + 8) * 1024 + cc) = hi;
      }
    }
  } else {
    __half* smb = smh; // 128 x 136 fp16 bounce
    #pragma unroll
    for (int mf = 0; mf < 4; mf++){
      int r = wm * 64 + mf * 16 + (lane >> 2);
      #pragma unroll
      for (int nf = 0; nf < 8; nf++){
        int cc = wn * 64 + nf * 8 + (lane & 3) * 2;
        *(__half2*)&smb[r * 136 + cc]       = __floats2half2_rn(acc[mf][nf][0], acc[mf][nf][1]);
        *(__half2*)&smb[(r + 8) * 136 + cc] = __floats2half2_rn(acc[mf][nf][2], acc[mf][nf][3]);
      }
    }
    __syncthreads();
    #pragma unroll
    for (int i = 0; i < 16; i++){
      int e = t + i * 128, rr = e >> 4, q = e & 15;
      int m = by * 128 + rr, n = m / 384, rem = m % 384, l = rem >> 5, c = rem & 31;
      int p = 32 + kb * 32 + c;
      *(uint4*)(g_P + ((size_t)((p * 64 + n) * 12 + l)) * 1024 + w0 + q * 8)
        = *(uint4*)&smb[rr * 136 + q * 8];
    }
  }
}

// stage 3 (fp16 mma): O[m][o] = sum_k P[k][m]*W2[o][k] + b[o]
// smem: As[4][16][136]=17408B at 0, Ws[64][232]=29696B at 17408. total 47104
#define G3SMEM 47104
__global__ __launch_bounds__(256, 2) void gemm3_k(const float* __restrict__ bias){
  extern __shared__ __half smh[];
  __half* Asm = smh;
  __half* Wsm = smh + 8704;   // 17408 B / 2
  const int t = threadIdx.x, lane = t & 31, wid = t >> 5;
  const size_t m0 = (size_t)blockIdx.x * 128;

  { // prologue G0: Ws (whole W) + As0
    #pragma unroll
    for (int i = 0; i < 7; i++){
      int idx = t + i * 256, r = idx / 28, q = idx % 28;
      cp16(Wsm + r * 232 + q * 8, g_W2 + r * 224 + q * 8);
    }
    int r = t >> 4, q = t & 15;
    cp16(Asm + r * 136 + q * 8, g_P + (size_t)r * 786432 + m0 + q * 8);
    cpcommit();
    // G1, G2: As1, As2
    cp16(Asm + 2176 + r * 136 + q * 8, g_P + (size_t)(16 + r) * 786432 + m0 + q * 8);
    cpcommit();
    cp16(Asm + 4352 + r * 136 + q * 8, g_P + (size_t)(32 + r) * 786432 + m0 + q * 8);
    cpcommit();
  }
  float acc[8][4];
  #pragma unroll
  for (int j = 0; j < 8; j++)
    #pragma unroll
    for (int q = 0; q < 4; q++) acc[j][q] = 0.f;

  const unsigned sbase = (unsigned)__cvta_generic_to_shared(smh);
  const unsigned wbase = sbase + 17408;
  const int tile = lane >> 3, rowin = lane & 7;
  // A (trans ldsm): stored [k][m]; addr row = k-part, col = m-part
  const unsigned aoff = ((tile >> 1) * 8 + rowin) * 272 + (wid * 16 + (tile & 1) * 8) * 2;
  // B (normal ldsm): Ws [o][k], row stride 232 halfs = 464 B
  const unsigned boff = ((tile >> 1) * 8 + rowin) * 464 + (tile & 1) * 16;

  for (int kt = 0; kt < 14; kt++){
    asm volatile("cp.async.wait_group 2;\n");
    __syncthreads();
    if (kt + 3 < 14){
      int buf = (kt + 3) & 3, r = t >> 4, q = t & 15;
      cp16(Asm + buf * 2176 + r * 136 + q * 8,
           g_P + (size_t)((kt + 3) * 16 + r) * 786432 + m0 + q * 8);
    }
    cpcommit();
    unsigned af[4], bf[8][2];
    ldsm4t(af, sbase + ((kt & 3) * 4352) + aoff);
    #pragma unroll
    for (int j = 0; j < 4; j++){
      unsigned r4[4];
      ldsm4(r4, wbase + boff + j * 7424 + kt * 32);
      bf[2*j][0] = r4[0]; bf[2*j][1] = r4[1];
      bf[2*j+1][0] = r4[2]; bf[2*j+1][1] = r4[3];
    }
    #pragma unroll
    for (int nf = 0; nf < 8; nf++) mma16(acc[nf], af, bf[nf]);
  }
  asm volatile("cp.async.wait_group 0;\n");

  size_t r = m0 + wid * 16 + (lane >> 2);
  #pragma unroll
  for (int nf = 0; nf < 8; nf++){
    int o = nf * 8 + (lane & 3) * 2;
    float b0 = __ldg(bias + o), b1 = __ldg(bias + o + 1);
    *(__half2*)(g_O + r * 64 + o)       = __floats2half2_rn(acc[nf][0] + b0, acc[nf][1] + b1);
    *(__half2*)(g_O + (r + 8) * 64 + o) = __floats2half2_rn(acc[nf][2] + b0, acc[nf][3] + b1);
  }
}

// O[(n,l,w)][o] fp16 -> out[n][o][w][l] fp32
__global__ void trans_k(float* __restrict__ out){
  __shared__ float sm[6144];
  int w0 = blockIdx.x * 8, n = blockIdx.y, t = threadIdx.x;
  for (int e = t; e < 6144; e += 256){
    int l = e / 512, rem = e % 512, w = rem >> 6, o = rem & 63;
    sm[e] = __half2float(g_O[((size_t)(n * 12 + l) * 1024 + w0 + w) * 64 + o]);
  }
  __syncthreads();
  for (int e = t; e < 6144; e += 256){
    int o = e / 96, rem = e % 96, w = rem / 12, l = rem % 12;
    out[((size_t)(n * 64 + o) * 1024 + w0 + w) * 12 + l] = sm[(l * 8 + w) * 64 + o];
  }
}

extern "C" void kernel_launch(void* const* d_in, const int* in_sizes, int n_in,
                              void* d_out, int out_size) {
  const float* x  = (const float*)d_in[0];
  const float* a0 = (const float*)d_in[1];
  const float* a1 = (const float*)d_in[2];
  const float* a2 = (const float*)d_in[3];
  const float* W  = (const float*)d_in[4];
  const float* b  = (const float*)d_in[5];
  float* out = (float*)d_out;
  cudaFuncSetAttribute(gemm_k, cudaFuncAttributeMaxDynamicSharedMemorySize, GSMEM);
  cudaFuncSetAttribute(gemm3_k, cudaFuncAttributeMaxDynamicSharedMemorySize, G3SMEM);
  pack_a_k<<<dim3(32, 32, 3), 256>>>(a0, a1, a2);
  pack_w_k<<<56, 256>>>(W);
  pack_x_k<<<4096, 256>>>(x);
  gemm_k<<<dim3(8, 8, 3), 128, GSMEM>>>(0);
  gemm_k<<<dim3(48, 192, 1), 128, GSMEM>>>(1);
  gemm3_k<<<6144, 256, G3SMEM>>>(b);
  trans_k<<<dim3(128, 64), 256>>>(out);
}

// round 15
// speedup vs baseline: 1.0322x; 1.0322x over previous
#include <cuda_runtime.h>
#include <cuda_fp16.h>
#include <cstdint>

__device__ __half g_X[25165824];    // [m=(n,l,c)][v] fp16
__device__ __half g_A[3145728];     // A [v][w] fp16
__device__ __half g_At[3145728];    // A^T [w][v] fp16
__device__ __half g_AsqT[3145728];  // (A^2)^T [w][v] fp16
__device__ __half g_P[176160768];   // planes [cc][n][l][w] fp16
__device__ __half g_O[50331648];    // [m=(n,l,w)][o] fp16
__device__ __half g_W2[14336];      // [o][k] fp16

__device__ __forceinline__ void cp16(void* s, const void* g){
  unsigned sa = (unsigned)__cvta_generic_to_shared(s);
  asm volatile("cp.async.cg.shared.global [%0], [%1], 16;\n" :: "r"(sa), "l"(g));
}
__device__ __forceinline__ void cpcommit(){ asm volatile("cp.async.commit_group;\n"); }
__device__ __forceinline__ void ldsm4(unsigned* r, unsigned a){
  asm volatile("ldmatrix.sync.aligned.m8n8.x4.shared.b16 {%0,%1,%2,%3}, [%4];"
    : "=r"(r[0]), "=r"(r[1]), "=r"(r[2]), "=r"(r[3]) : "r"(a));
}
__device__ __forceinline__ void ldsm4t(unsigned* r, unsigned a){
  asm volatile("ldmatrix.sync.aligned.m8n8.x4.trans.shared.b16 {%0,%1,%2,%3}, [%4];"
    : "=r"(r[0]), "=r"(r[1]), "=r"(r[2]), "=r"(r[3]) : "r"(a));
}
__device__ __forceinline__ void mma16(float* d, const unsigned* a, const unsigned* b){
  asm volatile("mma.sync.aligned.m16n8k16.row.col.f32.f16.f16.f32 "
    "{%0,%1,%2,%3},{%4,%5,%6,%7},{%8,%9},{%0,%1,%2,%3};\n"
    : "+f"(d[0]), "+f"(d[1]), "+f"(d[2]), "+f"(d[3])
    : "r"(a[0]), "r"(a[1]), "r"(a[2]), "r"(a[3]), "r"(b[0]), "r"(b[1]));
}

__global__ void pack_a_k(const float* __restrict__ a0, const float* __restrict__ a1,
                         const float* __restrict__ a2){
  __shared__ float tsm[32][33];
  int z = blockIdx.z;
  const float* A = (z == 0) ? a0 : ((z == 1) ? a1 : a2);
  size_t zo = (size_t)z << 20;
  int v0 = blockIdx.y * 32, w0 = blockIdx.x * 32;
  int cl = threadIdx.x & 31, rg = threadIdx.x >> 5;
  #pragma unroll
  for (int i = 0; i < 4; i++){
    int row = rg + i * 8;
    float val = A[(size_t)(v0 + row) * 1024 + w0 + cl];
    g_A[zo + (size_t)(v0 + row) * 1024 + w0 + cl] = __float2half_rn(val);
    tsm[row][cl] = val;
  }
  __syncthreads();
  #pragma unroll
  for (int i = 0; i < 4; i++){
    int wr = rg + i * 8;
    g_At[zo + (size_t)(w0 + wr) * 1024 + v0 + cl] = __float2half_rn(tsm[cl][wr]);
  }
}
__global__ void pack_w_k(const float* __restrict__ W){
  int i = blockIdx.x * 256 + threadIdx.x;
  if (i < 14336) g_W2[i] = __float2half_rn(W[i]);
}
__global__ void pack_x_k(const float* __restrict__ x){
  __shared__ float sm[6656];
  int nc = blockIdx.x >> 1, h = blockIdx.x & 1, t = threadIdx.x;
  int n = nc >> 5, c = nc & 31;
  const float* src = x + (size_t)nc * 12288 + h * 6144;
  for (int i = t; i < 6144; i += 256) sm[(i / 12) * 13 + (i % 12)] = src[i];
  __syncthreads();
  for (int l = 0; l < 12; l++){
    __half* d1 = g_X + ((size_t)((n * 12 + l) * 32 + c)) * 1024 + h * 512;
    __half* d2 = g_P + ((size_t)((c * 64 + n) * 12 + l)) * 1024 + h * 512;
    for (int v = t; v < 512; v += 256){
      __half r = __float2half_rn(sm[v * 13 + l]);
      d1[v] = r; d2[v] = r;
    }
  }
}

// fp16 GEMM: CTA 128x128, 4 warps of 64x64, KTILE=64, 3-stage ring, 2 CTAs/SM.
#define GSMEM 110592
__global__ __launch_bounds__(128, 2) void gemm_k(int mode){
  extern __shared__ __half smh[];
  const int t = threadIdx.x, lane = t & 31, wid = t >> 5;
  const int bx = blockIdx.x, by = blockIdx.y, bz = blockIdx.z;
  const __half *Ap, *Bp; int kb = 0, w0 = 0;
  if (mode == 0){
    size_t zo = (size_t)bz << 20;
    Ap = g_At + zo + (size_t)by * 131072;
    Bp = g_A  + zo + (size_t)bx * 131072;
  } else {
    Ap = g_X + (size_t)by * 131072;
    kb = bx >> 3; w0 = (bx & 7) * 128;
    Bp = ((kb & 1) ? g_AsqT : g_At) + ((size_t)(kb >> 1) << 20) + (size_t)w0 * 1024;
  }
  float acc[4][8][4];
  #pragma unroll
  for (int i = 0; i < 4; i++)
    #pragma unroll
    for (int j = 0; j < 8; j++)
      #pragma unroll
      for (int q = 0; q < 4; q++) acc[i][j][q] = 0.f;

  auto load_stage = [&](int kt, int s){
    __half* As = smh + s * 18432;
    __half* Bs = As + 9216;
    const __half* Ag = Ap + kt * 64;
    #pragma unroll
    for (int i = 0; i < 8; i++){
      int idx = t + i * 128, r = idx >> 3, q = idx & 7;
      cp16(As + r * 72 + q * 8, Ag + (size_t)r * 1024 + q * 8);
    }
    const __half* Bg = Bp + kt * 64;
    #pragma unroll
    for (int i = 0; i < 8; i++){
      int idx = t + i * 128, r = idx >> 3, q = idx & 7;
      cp16(Bs + r * 72 + q * 8, Bg + (size_t)r * 1024 + q * 8);
    }
  };
  load_stage(0, 0); cpcommit();
  load_stage(1, 1); cpcommit();

  const int wm = wid >> 1, wn = wid & 1;
  const unsigned sbase = (unsigned)__cvta_generic_to_shared(smh);
  const int tile = lane >> 3, rowin = lane & 7;
  const unsigned aoff = (wm * 64 + rowin + (tile & 1) * 8) * 144 + (tile >> 1) * 16;
  const unsigned boff = 18432 + (wn * 64 + (tile >> 1) * 8 + rowin) * 144 + (tile & 1) * 16;

  int sidx = 0;
  for (int kt = 0; kt < 16; kt++){
    asm volatile("cp.async.wait_group 1;\n");
    __syncthreads();
    if (kt + 2 < 16){
      int s2 = sidx + 2; if (s2 >= 3) s2 -= 3;
      load_stage(kt + 2, s2);
    }
    cpcommit();
    unsigned sst = sbase + sidx * 36864;
    #pragma unroll
    for (int ksp = 0; ksp < 2; ksp++){
      unsigned af[2][4][4], bf[2][8][2];
      #pragma unroll
      for (int k2 = 0; k2 < 2; k2++){
        int ks = ksp * 2 + k2;
        #pragma unroll
        for (int mf = 0; mf < 4; mf++)
          ldsm4(af[k2][mf], sst + aoff + mf * 2304 + ks * 32);
        #pragma unroll
        for (int j = 0; j < 4; j++){
          unsigned r4[4];
          ldsm4(r4, sst + boff + j * 2304 + ks * 32);
          bf[k2][2*j][0] = r4[0]; bf[k2][2*j][1] = r4[1];
          bf[k2][2*j+1][0] = r4[2]; bf[k2][2*j+1][1] = r4[3];
        }
      }
      #pragma unroll
      for (int k2 = 0; k2 < 2; k2++)
        #pragma unroll
        for (int mf = 0; mf < 4; mf++)
          #pragma unroll
          for (int nf = 0; nf < 8; nf++) mma16(acc[mf][nf], af[k2][mf], bf[k2][nf]);
    }
    if (++sidx == 3) sidx = 0;
  }
  asm volatile("cp.async.wait_group 0;\n");
  __syncthreads();

  if (mode == 0){
    #pragma unroll
    for (int mf = 0; mf < 4; mf++){
      int r = by * 128 + wm * 64 + mf * 16 + (lane >> 2);
      #pragma unroll
      for (int nf = 0; nf < 8; nf++){
        int cc = bx * 128 + wn * 64 + nf * 8 + (lane & 3) * 2;
        __half2 lo = __floats2half2_rn(acc[mf][nf][0], acc[mf][nf][1]);
        __half2 hi = __floats2half2_rn(acc[mf][nf][2], acc[mf][nf][3]);
        *(__half2*)(g_AsqT + ((size_t)bz << 20) + (size_t)r * 1024 + cc)       = lo;
        *(__half2*)(g_AsqT + ((size_t)bz << 20) + (size_t)(r + 8) * 1024 + cc) = hi;
      }
    }
  } else {
    __half* smb = smh;
    #pragma unroll
    for (int mf = 0; mf < 4; mf++){
      int r = wm * 64 + mf * 16 + (lane >> 2);
      #pragma unroll
      for (int nf = 0; nf < 8; nf++){
        int cc = wn * 64 + nf * 8 + (lane & 3) * 2;
        *(__half2*)&smb[r * 136 + cc]       = __floats2half2_rn(acc[mf][nf][0], acc[mf][nf][1]);
        *(__half2*)&smb[(r + 8) * 136 + cc] = __floats2half2_rn(acc[mf][nf][2], acc[mf][nf][3]);
      }
    }
    __syncthreads();
    #pragma unroll
    for (int i = 0; i < 16; i++){
      int e = t + i * 128, rr = e >> 4, q = e & 15;
      int m = by * 128 + rr, n = m / 384, rem = m % 384, l = rem >> 5, c = rem & 31;
      int p = 32 + kb * 32 + c;
      *(uint4*)(g_P + ((size_t)((p * 64 + n) * 12 + l)) * 1024 + w0 + q * 8)
        = *(uint4*)&smb[rr * 136 + q * 8];
    }
  }
}

// stage 3 (fp16 mma): CTA 256m x 64o, 8 warps of 32x64, 4-stage A ring, W resident.
// smem: As 4 x (16 x 264 halfs = 8448B) = 33792B, Ws 64x232 halfs = 29696B. total 63488
#define G3SMEM 63488
__global__ __launch_bounds__(256, 2) void gemm3_k(const float* __restrict__ bias){
  extern __shared__ __half smh[];
  __half* Asm = smh;
  __half* Wsm = smh + 16896;   // byte 33792
  const int t = threadIdx.x, lane = t & 31, wid = t >> 5;
  const size_t m0 = (size_t)blockIdx.x * 256;

  { // prologue: group0 = W + stage0; groups 1,2 = stages 1,2
    #pragma unroll
    for (int i = 0; i < 7; i++){
      int idx = t + i * 256, r = idx / 28, q = idx % 28;
      cp16(Wsm + r * 232 + q * 8, g_W2 + r * 224 + q * 8);
    }
    #pragma unroll
    for (int s = 0; s < 3; s++){
      #pragma unroll
      for (int i = 0; i < 2; i++){
        int idx = t + i * 256, r = idx >> 5, q = idx & 31;
        cp16(Asm + s * 4224 + r * 264 + q * 8,
             g_P + (size_t)(s * 16 + r) * 786432 + m0 + q * 8);
      }
      cpcommit();
    }
  }
  float acc[2][8][4];
  #pragma unroll
  for (int i = 0; i < 2; i++)
    #pragma unroll
    for (int j = 0; j < 8; j++)
      #pragma unroll
      for (int q = 0; q < 4; q++) acc[i][j][q] = 0.f;

  const unsigned sbase = (unsigned)__cvta_generic_to_shared(smh);
  const unsigned wbase = sbase + 33792;
  const int tile = lane >> 3, rowin = lane & 7;
  const unsigned aoff = ((tile >> 1) * 8 + rowin) * 528 + (wid * 32 + (tile & 1) * 8) * 2;
  const unsigned boff = ((tile >> 1) * 8 + rowin) * 464 + (tile & 1) * 16;

  for (int kt = 0; kt < 14; kt++){
    asm volatile("cp.async.wait_group 2;\n");
    __syncthreads();
    if (kt + 3 < 14){
      int buf = (kt + 3) & 3;
      #pragma unroll
      for (int i = 0; i < 2; i++){
        int idx = t + i * 256, r = idx >> 5, q = idx & 31;
        cp16(Asm + buf * 4224 + r * 264 + q * 8,
             g_P + (size_t)((kt + 3) * 16 + r) * 786432 + m0 + q * 8);
      }
    }
    cpcommit();
    unsigned abase = sbase + (kt & 3) * 8448;
    unsigned af[2][4], bf[8][2];
    ldsm4t(af[0], abase + aoff);
    ldsm4t(af[1], abase + aoff + 32);
    #pragma unroll
    for (int j = 0; j < 4; j++){
      unsigned r4[4];
      ldsm4(r4, wbase + boff + j * 7424 + kt * 32);
      bf[2*j][0] = r4[0]; bf[2*j][1] = r4[1];
      bf[2*j+1][0] = r4[2]; bf[2*j+1][1] = r4[3];
    }
    #pragma unroll
    for (int mf = 0; mf < 2; mf++)
      #pragma unroll
      for (int nf = 0; nf < 8; nf++) mma16(acc[mf][nf], af[mf], bf[nf]);
  }
  asm volatile("cp.async.wait_group 0;\n");

  #pragma unroll
  for (int mf = 0; mf < 2; mf++){
    size_t r = m0 + wid * 32 + mf * 16 + (lane >> 2);
    #pragma unroll
    for (int nf = 0; nf < 8; nf++){
      int o = nf * 8 + (lane & 3) * 2;
      float b0 = __ldg(bias + o), b1 = __ldg(bias + o + 1);
      *(__half2*)(g_O + r * 64 + o)       = __floats2half2_rn(acc[mf][nf][0] + b0, acc[mf][nf][1] + b1);
      *(__half2*)(g_O + (r + 8) * 64 + o) = __floats2half2_rn(acc[mf][nf][2] + b0, acc[mf][nf][3] + b1);
    }
  }
}

// O[(n,l,w)][o] fp16 -> out[n][o][w][l] fp32
__global__ void trans_k(float* __restrict__ out){
  __shared__ float sm[6144];
  int w0 = blockIdx.x * 8, n = blockIdx.y, t = threadIdx.x;
  for (int e = t; e < 6144; e += 256){
    int l = e / 512, rem = e % 512, w = rem >> 6, o = rem & 63;
    sm[e] = __half2float(g_O[((size_t)(n * 12 + l) * 1024 + w0 + w) * 64 + o]);
  }
  __syncthreads();
  for (int e = t; e < 6144; e += 256){
    int o = e / 96, rem = e % 96, w = rem / 12, l = rem % 12;
    out[((size_t)(n * 64 + o) * 1024 + w0 + w) * 12 + l] = sm[(l * 8 + w) * 64 + o];
  }
}

extern "C" void kernel_launch(void* const* d_in, const int* in_sizes, int n_in,
                              void* d_out, int out_size) {
  const float* x  = (const float*)d_in[0];
  const float* a0 = (const float*)d_in[1];
  const float* a1 = (const float*)d_in[2];
  const float* a2 = (const float*)d_in[3];
  const float* W  = (const float*)d_in[4];
  const float* b  = (const float*)d_in[5];
  float* out = (float*)d_out;
  cudaFuncSetAttribute(gemm_k, cudaFuncAttributeMaxDynamicSharedMemorySize, GSMEM);
  cudaFuncSetAttribute(gemm3_k, cudaFuncAttributeMaxDynamicSharedMemorySize, G3SMEM);

  cudaStream_t s2;
  cudaStreamCreateWithFlags(&s2, cudaStreamNonBlocking);
  cudaEvent_t e1, e2;
  cudaEventCreateWithFlags(&e1, cudaEventDisableTiming);
  cudaEventCreateWithFlags(&e2, cudaEventDisableTiming);

  // fork: pack_x runs concurrently with pack_a/pack_w/mode0
  cudaEventRecord(e1, 0);
  cudaStreamWaitEvent(s2, e1, 0);
  pack_x_k<<<4096, 256, 0, s2>>>(x);
  cudaEventRecord(e2, s2);

  pack_a_k<<<dim3(32, 32, 3), 256>>>(a0, a1, a2);
  pack_w_k<<<56, 256>>>(W);
  gemm_k<<<dim3(8, 8, 3), 128, GSMEM>>>(0);

  cudaStreamWaitEvent(0, e2, 0);   // join before mode1 (needs g_X, g_P x-planes)
  gemm_k<<<dim3(48, 192, 1), 128, GSMEM>>>(1);
  gemm3_k<<<3072, 256, G3SMEM>>>(b);
  trans_k<<<dim3(128, 64), 256>>>(out);

  cudaEventDestroy(e1);
  cudaEventDestroy(e2);
  cudaStreamDestroy(s2);
}

// round 16
// speedup vs baseline: 1.0484x; 1.0158x over previous
#include <cuda_runtime.h>
#include <cuda_fp16.h>
#include <cstdint>

__device__ __half g_X[25165824];    // [m=(n,l,c)][v] fp16
__device__ __half g_A[3145728];     // A [v][w] fp16
__device__ __half g_At[3145728];    // A^T [w][v] fp16
__device__ __half g_AsqT[3145728];  // (A^2)^T [w][v] fp16
__device__ __half g_P[176160768];   // planes [cc][n][l][w] fp16
__device__ __half g_O[50331648];    // [m=(n,l,w)][o] fp16
__device__ __half g_W2[14336];      // [o][k] fp16

__device__ __forceinline__ void cp16(void* s, const void* g){
  unsigned sa = (unsigned)__cvta_generic_to_shared(s);
  asm volatile("cp.async.cg.shared.global [%0], [%1], 16;\n" :: "r"(sa), "l"(g));
}
__device__ __forceinline__ void cpcommit(){ asm volatile("cp.async.commit_group;\n"); }
__device__ __forceinline__ void ldsm4(unsigned* r, unsigned a){
  asm volatile("ldmatrix.sync.aligned.m8n8.x4.shared.b16 {%0,%1,%2,%3}, [%4];"
    : "=r"(r[0]), "=r"(r[1]), "=r"(r[2]), "=r"(r[3]) : "r"(a));
}
__device__ __forceinline__ void ldsm4t(unsigned* r, unsigned a){
  asm volatile("ldmatrix.sync.aligned.m8n8.x4.trans.shared.b16 {%0,%1,%2,%3}, [%4];"
    : "=r"(r[0]), "=r"(r[1]), "=r"(r[2]), "=r"(r[3]) : "r"(a));
}
__device__ __forceinline__ void mma16(float* d, const unsigned* a, const unsigned* b){
  asm volatile("mma.sync.aligned.m16n8k16.row.col.f32.f16.f16.f32 "
    "{%0,%1,%2,%3},{%4,%5,%6,%7},{%8,%9},{%0,%1,%2,%3};\n"
    : "+f"(d[0]), "+f"(d[1]), "+f"(d[2]), "+f"(d[3])
    : "r"(a[0]), "r"(a[1]), "r"(a[2]), "r"(a[3]), "r"(b[0]), "r"(b[1]));
}

__global__ void pack_a_k(const float* __restrict__ a0, const float* __restrict__ a1,
                         const float* __restrict__ a2){
  __shared__ float tsm[32][33];
  int z = blockIdx.z;
  const float* A = (z == 0) ? a0 : ((z == 1) ? a1 : a2);
  size_t zo = (size_t)z << 20;
  int v0 = blockIdx.y * 32, w0 = blockIdx.x * 32;
  int cl = threadIdx.x & 31, rg = threadIdx.x >> 5;
  #pragma unroll
  for (int i = 0; i < 4; i++){
    int row = rg + i * 8;
    float val = A[(size_t)(v0 + row) * 1024 + w0 + cl];
    g_A[zo + (size_t)(v0 + row) * 1024 + w0 + cl] = __float2half_rn(val);
    tsm[row][cl] = val;
  }
  __syncthreads();
  #pragma unroll
  for (int i = 0; i < 4; i++){
    int wr = rg + i * 8;
    g_At[zo + (size_t)(w0 + wr) * 1024 + v0 + cl] = __float2half_rn(tsm[cl][wr]);
  }
}
__global__ void pack_w_k(const float* __restrict__ W){
  int i = blockIdx.x * 256 + threadIdx.x;
  if (i < 14336) g_W2[i] = __float2half_rn(W[i]);
}
__global__ void pack_x_k(const float* __restrict__ x){
  __shared__ float sm[6656];
  int nc = blockIdx.x >> 1, h = blockIdx.x & 1, t = threadIdx.x;
  int n = nc >> 5, c = nc & 31;
  const float* src = x + (size_t)nc * 12288 + h * 6144;
  for (int i = t; i < 6144; i += 256) sm[(i / 12) * 13 + (i % 12)] = src[i];
  __syncthreads();
  for (int l = 0; l < 12; l++){
    __half* d1 = g_X + ((size_t)((n * 12 + l) * 32 + c)) * 1024 + h * 512;
    __half* d2 = g_P + ((size_t)((c * 64 + n) * 12 + l)) * 1024 + h * 512;
    for (int v = t; v < 512; v += 256){
      __half r = __float2half_rn(sm[v * 13 + l]);
      d1[v] = r; d2[v] = r;
    }
  }
}

// fp16 GEMM: CTA 128x128, 4 warps of 64x64, KTILE=64, 3-stage ring, 2 CTAs/SM.
// Inner loop: register double-buffered fragments (LDSM of ks+1 overlaps MMA of ks).
#define GSMEM 110592
__global__ __launch_bounds__(128, 2) void gemm_k(int mode, int by0){
  extern __shared__ __half smh[];
  const int t = threadIdx.x, lane = t & 31, wid = t >> 5;
  const int bx = blockIdx.x, by = blockIdx.y + by0, bz = blockIdx.z;
  const __half *Ap, *Bp; int kb = 0, w0 = 0;
  if (mode == 0){
    size_t zo = (size_t)bz << 20;
    Ap = g_At + zo + (size_t)by * 131072;
    Bp = g_A  + zo + (size_t)bx * 131072;
  } else {
    Ap = g_X + (size_t)by * 131072;
    kb = bx >> 3; w0 = (bx & 7) * 128;
    Bp = ((kb & 1) ? g_AsqT : g_At) + ((size_t)(kb >> 1) << 20) + (size_t)w0 * 1024;
  }
  float acc[4][8][4];
  #pragma unroll
  for (int i = 0; i < 4; i++)
    #pragma unroll
    for (int j = 0; j < 8; j++)
      #pragma unroll
      for (int q = 0; q < 4; q++) acc[i][j][q] = 0.f;

  auto load_stage = [&](int kt, int s){
    __half* As = smh + s * 18432;
    __half* Bs = As + 9216;
    const __half* Ag = Ap + kt * 64;
    #pragma unroll
    for (int i = 0; i < 8; i++){
      int idx = t + i * 128, r = idx >> 3, q = idx & 7;
      cp16(As + r * 72 + q * 8, Ag + (size_t)r * 1024 + q * 8);
    }
    const __half* Bg = Bp + kt * 64;
    #pragma unroll
    for (int i = 0; i < 8; i++){
      int idx = t + i * 128, r = idx >> 3, q = idx & 7;
      cp16(Bs + r * 72 + q * 8, Bg + (size_t)r * 1024 + q * 8);
    }
  };
  load_stage(0, 0); cpcommit();
  load_stage(1, 1); cpcommit();

  const int wm = wid >> 1, wn = wid & 1;
  const unsigned sbase = (unsigned)__cvta_generic_to_shared(smh);
  const int tile = lane >> 3, rowin = lane & 7;
  const unsigned aoff = (wm * 64 + rowin + (tile & 1) * 8) * 144 + (tile >> 1) * 16;
  const unsigned boff = 18432 + (wn * 64 + (tile >> 1) * 8 + rowin) * 144 + (tile & 1) * 16;

  int sidx = 0;
  for (int kt = 0; kt < 16; kt++){
    asm volatile("cp.async.wait_group 1;\n");
    __syncthreads();
    if (kt + 2 < 16){
      int s2 = sidx + 2; if (s2 >= 3) s2 -= 3;
      load_stage(kt + 2, s2);
    }
    cpcommit();
    unsigned sst = sbase + sidx * 36864;
    unsigned af[2][4][4], bf[2][8][2];
    auto ldfrag = [&](int ks, int b){
      #pragma unroll
      for (int mf = 0; mf < 4; mf++)
        ldsm4(af[b][mf], sst + aoff + mf * 2304 + ks * 32);
      #pragma unroll
      for (int j = 0; j < 4; j++){
        unsigned r4[4];
        ldsm4(r4, sst + boff + j * 2304 + ks * 32);
        bf[b][2*j][0] = r4[0]; bf[b][2*j][1] = r4[1];
        bf[b][2*j+1][0] = r4[2]; bf[b][2*j+1][1] = r4[3];
      }
    };
    ldfrag(0, 0);
    #pragma unroll
    for (int ks = 0; ks < 4; ks++){
      int cur = ks & 1;
      if (ks < 3) ldfrag(ks + 1, cur ^ 1);
      #pragma unroll
      for (int mf = 0; mf < 4; mf++)
        #pragma unroll
        for (int nf = 0; nf < 8; nf++) mma16(acc[mf][nf], af[cur][mf], bf[cur][nf]);
    }
    if (++sidx == 3) sidx = 0;
  }
  asm volatile("cp.async.wait_group 0;\n");
  __syncthreads();

  if (mode == 0){
    #pragma unroll
    for (int mf = 0; mf < 4; mf++){
      int r = by * 128 + wm * 64 + mf * 16 + (lane >> 2);
      #pragma unroll
      for (int nf = 0; nf < 8; nf++){
        int cc = bx * 128 + wn * 64 + nf * 8 + (lane & 3) * 2;
        __half2 lo = __floats2half2_rn(acc[mf][nf][0], acc[mf][nf][1]);
        __half2 hi = __floats2half2_rn(acc[mf][nf][2], acc[mf][nf][3]);
        *(__half2*)(g_AsqT + ((size_t)bz << 20) + (size_t)r * 1024 + cc)       = lo;
        *(__half2*)(g_AsqT + ((size_t)bz << 20) + (size_t)(r + 8) * 1024 + cc) = hi;
      }
    }
  } else {
    __half* smb = smh;
    #pragma unroll
    for (int mf = 0; mf < 4; mf++){
      int r = wm * 64 + mf * 16 + (lane >> 2);
      #pragma unroll
      for (int nf = 0; nf < 8; nf++){
        int cc = wn * 64 + nf * 8 + (lane & 3) * 2;
        *(__half2*)&smb[r * 136 + cc]       = __floats2half2_rn(acc[mf][nf][0], acc[mf][nf][1]);
        *(__half2*)&smb[(r + 8) * 136 + cc] = __floats2half2_rn(acc[mf][nf][2], acc[mf][nf][3]);
      }
    }
    __syncthreads();
    #pragma unroll
    for (int i = 0; i < 16; i++){
      int e = t + i * 128, rr = e >> 4, q = e & 15;
      int m = by * 128 + rr, n = m / 384, rem = m % 384, l = rem >> 5, c = rem & 31;
      int p = 32 + kb * 32 + c;
      *(uint4*)(g_P + ((size_t)((p * 64 + n) * 12 + l)) * 1024 + w0 + q * 8)
        = *(uint4*)&smb[rr * 136 + q * 8];
    }
  }
}

// stage 3 (fp16 mma): CTA 256m x 64o, 8 warps of 32x64, 4-stage A ring, W resident.
#define G3SMEM 63488
__global__ __launch_bounds__(256, 2) void gemm3_k(const float* __restrict__ bias, int blk0){
  extern __shared__ __half smh[];
  __half* Asm = smh;
  __half* Wsm = smh + 16896;
  const int t = threadIdx.x, lane = t & 31, wid = t >> 5;
  const size_t m0 = (size_t)(blk0 + blockIdx.x) * 256;

  {
    #pragma unroll
    for (int i = 0; i < 7; i++){
      int idx = t + i * 256, r = idx / 28, q = idx % 28;
      cp16(Wsm + r * 232 + q * 8, g_W2 + r * 224 + q * 8);
    }
    #pragma unroll
    for (int s = 0; s < 3; s++){
      #pragma unroll
      for (int i = 0; i < 2; i++){
        int idx = t + i * 256, r = idx >> 5, q = idx & 31;
        cp16(Asm + s * 4224 + r * 264 + q * 8,
             g_P + (size_t)(s * 16 + r) * 786432 + m0 + q * 8);
      }
      cpcommit();
    }
  }
  float acc[2][8][4];
  #pragma unroll
  for (int i = 0; i < 2; i++)
    #pragma unroll
    for (int j = 0; j < 8; j++)
      #pragma unroll
      for (int q = 0; q < 4; q++) acc[i][j][q] = 0.f;

  const unsigned sbase = (unsigned)__cvta_generic_to_shared(smh);
  const unsigned wbase = sbase + 33792;
  const int tile = lane >> 3, rowin = lane & 7;
  const unsigned aoff = ((tile >> 1) * 8 + rowin) * 528 + (wid * 32 + (tile & 1) * 8) * 2;
  const unsigned boff = ((tile >> 1) * 8 + rowin) * 464 + (tile & 1) * 16;

  for (int kt = 0; kt < 14; kt++){
    asm volatile("cp.async.wait_group 2;\n");
    __syncthreads();
    if (kt + 3 < 14){
      int buf = (kt + 3) & 3;
      #pragma unroll
      for (int i = 0; i < 2; i++){
        int idx = t + i * 256, r = idx >> 5, q = idx & 31;
        cp16(Asm + buf * 4224 + r * 264 + q * 8,
             g_P + (size_t)((kt + 3) * 16 + r) * 786432 + m0 + q * 8);
      }
    }
    cpcommit();
    unsigned abase = sbase + (kt & 3) * 8448;
    unsigned af[2][4], bf[8][2];
    ldsm4t(af[0], abase + aoff);
    ldsm4t(af[1], abase + aoff + 32);
    #pragma unroll
    for (int j = 0; j < 4; j++){
      unsigned r4[4];
      ldsm4(r4, wbase + boff + j * 7424 + kt * 32);
      bf[2*j][0] = r4[0]; bf[2*j][1] = r4[1];
      bf[2*j+1][0] = r4[2]; bf[2*j+1][1] = r4[3];
    }
    #pragma unroll
    for (int mf = 0; mf < 2; mf++)
      #pragma unroll
      for (int nf = 0; nf < 8; nf++) mma16(acc[mf][nf], af[mf], bf[nf]);
  }
  asm volatile("cp.async.wait_group 0;\n");

  #pragma unroll
  for (int mf = 0; mf < 2; mf++){
    size_t r = m0 + wid * 32 + mf * 16 + (lane >> 2);
    #pragma unroll
    for (int nf = 0; nf < 8; nf++){
      int o = nf * 8 + (lane & 3) * 2;
      float b0 = __ldg(bias + o), b1 = __ldg(bias + o + 1);
      *(__half2*)(g_O + r * 64 + o)       = __floats2half2_rn(acc[mf][nf][0] + b0, acc[mf][nf][1] + b1);
      *(__half2*)(g_O + (r + 8) * 64 + o) = __floats2half2_rn(acc[mf][nf][2] + b0, acc[mf][nf][3] + b1);
    }
  }
}

// O[(n,l,w)][o] fp16 -> out[n][o][w][l] fp32
__global__ void trans_k(float* __restrict__ out, int n0){
  __shared__ float sm[6144];
  int w0 = blockIdx.x * 8, n = n0 + blockIdx.y, t = threadIdx.x;
  for (int e = t; e < 6144; e += 256){
    int l = e / 512, rem = e % 512, w = rem >> 6, o = rem & 63;
    sm[e] = __half2float(g_O[((size_t)(n * 12 + l) * 1024 + w0 + w) * 64 + o]);
  }
  __syncthreads();
  for (int e = t; e < 6144; e += 256){
    int o = e / 96, rem = e % 96, w = rem / 12, l = rem % 12;
    out[((size_t)(n * 64 + o) * 1024 + w0 + w) * 12 + l] = sm[(l * 8 + w) * 64 + o];
  }
}

extern "C" void kernel_launch(void* const* d_in, const int* in_sizes, int n_in,
                              void* d_out, int out_size) {
  const float* x  = (const float*)d_in[0];
  const float* a0 = (const float*)d_in[1];
  const float* a1 = (const float*)d_in[2];
  const float* a2 = (const float*)d_in[3];
  const float* W  = (const float*)d_in[4];
  const float* b  = (const float*)d_in[5];
  float* out = (float*)d_out;
  cudaFuncSetAttribute(gemm_k, cudaFuncAttributeMaxDynamicSharedMemorySize, GSMEM);
  cudaFuncSetAttribute(gemm3_k, cudaFuncAttributeMaxDynamicSharedMemorySize, G3SMEM);

  cudaStream_t s2;
  cudaStreamCreateWithFlags(&s2, cudaStreamNonBlocking);
  cudaEvent_t e1, e2, e3, e6;
  cudaEventCreateWithFlags(&e1, cudaEventDisableTiming);
  cudaEventCreateWithFlags(&e2, cudaEventDisableTiming);
  cudaEventCreateWithFlags(&e3, cudaEventDisableTiming);
  cudaEventCreateWithFlags(&e6, cudaEventDisableTiming);

  // fork: pack_x concurrent with pack_a/pack_w/mode0
  cudaEventRecord(e1, 0);
  cudaStreamWaitEvent(s2, e1, 0);
  pack_x_k<<<4096, 256, 0, s2>>>(x);
  cudaEventRecord(e2, s2);

  pack_a_k<<<dim3(32, 32, 3), 256>>>(a0, a1, a2);
  pack_w_k<<<56, 256>>>(W);
  gemm_k<<<dim3(8, 8, 3), 128, GSMEM>>>(0, 0);

  cudaStreamWaitEvent(0, e2, 0);   // mode1 needs g_X + g_P x-planes
  gemm_k<<<dim3(48, 96, 1), 128, GSMEM>>>(1, 0);    // by 0..95 (n 0..31)
  cudaEventRecord(e3, 0);
  gemm_k<<<dim3(48, 96, 1), 128, GSMEM>>>(1, 96);   // by 96..191 (n 32..63)

  // tail half 0 on s2, overlapping mode1 half 1
  cudaStreamWaitEvent(s2, e3, 0);
  gemm3_k<<<1536, 256, G3SMEM, s2>>>(b, 0);
  trans_k<<<dim3(128, 32), 256, 0, s2>>>(out, 0);
  cudaEventRecord(e6, s2);

  // tail half 1 on main stream
  gemm3_k<<<1536, 256, G3SMEM>>>(b, 1536);
  trans_k<<<dim3(128, 32), 256>>>(out, 32);
  cudaStreamWaitEvent(0, e6, 0);   // join fork before returning

  cudaEventDestroy(e1);
  cudaEventDestroy(e2);
  cudaEventDestroy(e3);
  cudaEventDestroy(e6);
  cudaStreamDestroy(s2);
}